// round 12
// baseline (speedup 1.0000x reference)
#include <cuda_runtime.h>
#include <math.h>

#define C_DIM 1024
#define NQ 10            // gated queries (ref has NQ+1 = 11 query rows)
#define NP 5             // q-pairs
#define MAXN 100000
#define K1_RPW 8         // rows per warp per tile
#define K1_WARPS 8
#define K1_RPB (K1_RPW * K1_WARPS)   // 64 rows per tile
#define K1_GRID 148                  // persistent, 1 CTA/SM (8 warps, ~210 regs)
#define K2_TILE 128
#define K2_GRID 592                  // persistent, 4 CTAs/SM

typedef unsigned long long u64;

// ---- scratch (static device memory; no allocations) ----
__device__ u64   g_Qp[NP * C_DIM];                    // packed q-pair diffs, SWIZZLED
__device__ float g_logits[(size_t)NQ * MAXN];         // [q][n], 4 MB
__device__ float g_bmax[(size_t)K1_GRID * NQ];        // per-block max partials
__device__ float g_M[NQ];                             // per-q max logit
__device__ float g_Z[NQ];                             // per-q softmax denom
__device__ float g_partial[(size_t)K2_GRID * C_DIM];  // pass-2 partials
__device__ float g_pooled[C_DIM];

// ---- packed f32x2 helpers ----
__device__ __forceinline__ u64 f2fma(u64 a, u64 b, u64 c) {
    u64 d;
    asm("fma.rn.f32x2 %0, %1, %2, %3;" : "=l"(d) : "l"(a), "l"(b), "l"(c));
    return d;
}
__device__ __forceinline__ u64 f2add(u64 a, u64 b) {
    u64 d;
    asm("add.rn.f32x2 %0, %1, %2;" : "=l"(d) : "l"(a), "l"(b));
    return d;
}
__device__ __forceinline__ u64 fdup(float x) {
    u64 d;
    asm("mov.b64 %0, {%1, %1};" : "=l"(d) : "f"(x));
    return d;
}
__device__ __forceinline__ u64 fpack(float lo, float hi) {
    u64 d;
    asm("mov.b64 %0, {%1, %2};" : "=l"(d) : "f"(lo), "f"(hi));
    return d;
}
__device__ __forceinline__ float f2lo(u64 v) { return __uint_as_float((unsigned)v); }
__device__ __forceinline__ float f2hi(u64 v) { return __uint_as_float((unsigned)(v >> 32)); }
__device__ __forceinline__ float f2sum(u64 v) { return f2lo(v) + f2hi(v); }
__device__ __forceinline__ u64 shfl_xor64(u64 v, int off) {
    unsigned lo = (unsigned)v, hi = (unsigned)(v >> 32);
    lo = __shfl_xor_sync(0xffffffffu, lo, off);
    hi = __shfl_xor_sync(0xffffffffu, hi, off);
    return (u64)lo | ((u64)hi << 32);
}

// swizzle within each 128-col chunk so lane l's 4 cols {4l..4l+3} are two
// contiguous 16B LDS.128 loads: first 64 slots = cols with c%4 in {0,1},
// second 64 = c%4 in {2,3}
__device__ __forceinline__ int qswz(int c) {
    int kkc = c >> 7;
    int w = c & 127;
    int p4 = w >> 2;
    int r = w & 3;
    int slot = (r < 2) ? (p4 * 2 + r) : (64 + p4 * 2 + (r & 1));
    return kkc * 128 + slot;
}

// ============================================================
// K0: normalize Q rows, build packed+swizzled Qp; init Z/pooled
// ============================================================
__global__ void k0_prep(const float* __restrict__ Q) {
    __shared__ float s_inv[NQ + 1];
    __shared__ float s_red[128];
    int t = threadIdx.x;
    for (int q = 0; q < NQ + 1; q++) {
        float ss = 0.f;
        for (int c = t; c < C_DIM; c += 128) {
            float v = Q[q * C_DIM + c];
            ss = fmaf(v, v, ss);
        }
        s_red[t] = ss;
        __syncthreads();
        for (int s = 64; s > 0; s >>= 1) {
            if (t < s) s_red[t] += s_red[t + s];
            __syncthreads();
        }
        if (t == 0) s_inv[q] = 1.0f / fmaxf(sqrtf(s_red[0]), 1e-12f);
        __syncthreads();
    }
    float invL = s_inv[NQ];
    for (int c = t; c < C_DIM; c += 128) {
        float ql = Q[NQ * C_DIM + c] * invL;
        int sz = qswz(c);
#pragma unroll
        for (int p = 0; p < NP; p++) {
            float lo = Q[(2 * p) * C_DIM + c] * s_inv[2 * p] - ql;
            float hi = Q[(2 * p + 1) * C_DIM + c] * s_inv[2 * p + 1] - ql;
            g_Qp[p * C_DIM + sz] = fpack(lo, hi);
        }
    }
    if (t < NQ) g_Z[t] = 0.f;
    for (int c = t; c < C_DIM; c += 128) g_pooled[c] = 0.f;
}

// ============================================================
// K1: logits[q][n] = 100 * (Qd[q] . X[n]) / max(||X[n]||, eps)
// RPW=8, 1 CTA/SM, 16B/lane (LDG.128 X, conflict-free LDS.128 Q),
// depth-2 cross-tile prefetch, 8-row pair-merge reduction.
// ============================================================
__global__ __launch_bounds__(256, 1) void k1_logits(const float* __restrict__ X,
                                                    int N, int ntiles) {
    __shared__ u64 s_qp[NP * C_DIM];            // 40 KB
    __shared__ float s_wmax[K1_WARPS][NQ];
    int t = threadIdx.x;
    int warp = t >> 5, lane = t & 31;
    for (int i = t; i < NP * C_DIM; i += 256) s_qp[i] = g_Qp[i];
    if (t < K1_WARPS * NQ) ((float*)s_wmax)[t] = -1e30f;
    __syncthreads();

    bool hi16 = (lane & 16) != 0;

    // balanced contiguous tile range for this block
    int tb0 = (int)((long long)blockIdx.x * ntiles / gridDim.x);
    int tb1 = (int)((long long)(blockIdx.x + 1) * ntiles / gridDim.x);

    int ro[K1_RPW];
    {
        int row0 = tb0 * K1_RPB + warp * K1_RPW;
#pragma unroll
        for (int j = 0; j < K1_RPW; j++) {
            int r = row0 + j;
            if (r > N - 1) r = N - 1;
            ro[j] = r * C_DIM + 4 * lane;
        }
    }

    // preload chunks 0,1 of first tile (16B/lane)
    ulonglong2 A[K1_RPW], B[K1_RPW];
#pragma unroll
    for (int j = 0; j < K1_RPW; j++) A[j] = __ldcs((const ulonglong2*)(X + ro[j]));
#pragma unroll
    for (int j = 0; j < K1_RPW; j++) B[j] = __ldcs((const ulonglong2*)(X + ro[j] + 128));

    for (int tile = tb0; tile < tb1; tile++) {
        int row0 = tile * K1_RPB + warp * K1_RPW;
        int row0n = (tile + 1) * K1_RPB + warp * K1_RPW;

        u64 acc[K1_RPW][NP];
        u64 nacc[K1_RPW];
#pragma unroll
        for (int j = 0; j < K1_RPW; j++) {
            nacc[j] = 0ull;
#pragma unroll
            for (int p = 0; p < NP; p++) acc[j][p] = 0ull;
        }

#pragma unroll
        for (int kk = 0; kk < 8; kk++) {
            ulonglong2* xb = (kk & 1) ? B : A;
            int qb = kk * 128 + 2 * lane;   // u64 index within chunk

            // ---- half A: cols 4l, 4l+1 ----
            {
                ulonglong2 qv[NP];
#pragma unroll
                for (int p = 0; p < NP; p++)
                    qv[p] = *(const ulonglong2*)&s_qp[p * C_DIM + qb];
#pragma unroll
                for (int j = 0; j < K1_RPW; j++) {
                    u64 xx = xb[j].x;
                    u64 d0 = fdup(f2lo(xx));
                    u64 d1 = fdup(f2hi(xx));
                    nacc[j] = f2fma(xx, xx, nacc[j]);
#pragma unroll
                    for (int p = 0; p < NP; p++) {
                        acc[j][p] = f2fma(d0, qv[p].x, acc[j][p]);
                        acc[j][p] = f2fma(d1, qv[p].y, acc[j][p]);
                    }
                }
            }
            // ---- half B: cols 4l+2, 4l+3 ----
            {
                ulonglong2 qv[NP];
#pragma unroll
                for (int p = 0; p < NP; p++)
                    qv[p] = *(const ulonglong2*)&s_qp[p * C_DIM + qb + 64];
#pragma unroll
                for (int j = 0; j < K1_RPW; j++) {
                    u64 xy = xb[j].y;
                    u64 d2 = fdup(f2lo(xy));
                    u64 d3 = fdup(f2hi(xy));
                    nacc[j] = f2fma(xy, xy, nacc[j]);
#pragma unroll
                    for (int p = 0; p < NP; p++) {
                        acc[j][p] = f2fma(d2, qv[p].x, acc[j][p]);
                        acc[j][p] = f2fma(d3, qv[p].y, acc[j][p]);
                    }
                }
            }
            // ---- refill this buffer (depth-2; cross-tile for kk>=6) ----
            if (kk < 6) {
                int nb = (kk + 2) * 128;
#pragma unroll
                for (int j = 0; j < K1_RPW; j++)
                    xb[j] = __ldcs((const ulonglong2*)(X + ro[j] + nb));
            } else {
                int nb = (kk - 6) * 128;
#pragma unroll
                for (int j = 0; j < K1_RPW; j++) {
                    int rn = row0n + j;
                    if (rn > N - 1) rn = N - 1;
                    xb[j] = __ldcs((const ulonglong2*)(X + rn * C_DIM + 4 * lane + nb));
                }
            }
        }

        // ---- 8-row pair-merge reduction ----
        float ns[K1_RPW];
#pragma unroll
        for (int j = 0; j < K1_RPW; j++) ns[j] = f2sum(nacc[j]);

        u64 nK1 = hi16 ? fpack(ns[1], ns[3]) : fpack(ns[0], ns[2]);
        u64 nS1 = hi16 ? fpack(ns[0], ns[2]) : fpack(ns[1], ns[3]);
        u64 nm1 = f2add(nK1, shfl_xor64(nS1, 16));
        u64 nK2 = hi16 ? fpack(ns[5], ns[7]) : fpack(ns[4], ns[6]);
        u64 nS2 = hi16 ? fpack(ns[4], ns[6]) : fpack(ns[5], ns[7]);
        u64 nm2 = f2add(nK2, shfl_xor64(nS2, 16));

        u64 Av[NP], Bv[NP], Cv[NP], Dv[NP];
#pragma unroll
        for (int p = 0; p < NP; p++) {
            u64 k0v = hi16 ? acc[1][p] : acc[0][p];
            u64 s0v = hi16 ? acc[0][p] : acc[1][p];
            Av[p] = f2add(k0v, shfl_xor64(s0v, 16));
            u64 k1v = hi16 ? acc[3][p] : acc[2][p];
            u64 s1v = hi16 ? acc[2][p] : acc[3][p];
            Bv[p] = f2add(k1v, shfl_xor64(s1v, 16));
            u64 k2v = hi16 ? acc[5][p] : acc[4][p];
            u64 s2v = hi16 ? acc[4][p] : acc[5][p];
            Cv[p] = f2add(k2v, shfl_xor64(s2v, 16));
            u64 k3v = hi16 ? acc[7][p] : acc[6][p];
            u64 s3v = hi16 ? acc[6][p] : acc[7][p];
            Dv[p] = f2add(k3v, shfl_xor64(s3v, 16));
        }

#pragma unroll
        for (int off = 8; off; off >>= 1) {
            nm1 = f2add(nm1, shfl_xor64(nm1, off));
            nm2 = f2add(nm2, shfl_xor64(nm2, off));
#pragma unroll
            for (int p = 0; p < NP; p++) {
                Av[p] = f2add(Av[p], shfl_xor64(Av[p], off));
                Bv[p] = f2add(Bv[p], shfl_xor64(Bv[p], off));
                Cv[p] = f2add(Cv[p], shfl_xor64(Cv[p], off));
                Dv[p] = f2add(Dv[p], shfl_xor64(Dv[p], off));
            }
        }

        // half-warp owns rows rA=row0+(hi16?1:0), rB=rA+2, rC=rA+4, rD=rA+6
        int rA = row0 + (hi16 ? 1 : 0);
        int rB = rA + 2, rC = rA + 4, rD = rA + 6;
        float scA = 100.0f / fmaxf(sqrtf(f2lo(nm1)), 1e-12f);
        float scB = 100.0f / fmaxf(sqrtf(f2hi(nm1)), 1e-12f);
        float scC = 100.0f / fmaxf(sqrtf(f2lo(nm2)), 1e-12f);
        float scD = 100.0f / fmaxf(sqrtf(f2hi(nm2)), 1e-12f);
        bool vA = (rA < N), vB = (rB < N), vC = (rC < N), vD = (rD < N);
        bool storer = (lane == 0) || (lane == 16);
#pragma unroll
        for (int p = 0; p < NP; p++) {
            float a0 = f2lo(Av[p]) * scA, a1 = f2hi(Av[p]) * scA;
            float b0 = f2lo(Bv[p]) * scB, b1 = f2hi(Bv[p]) * scB;
            float c0 = f2lo(Cv[p]) * scC, c1 = f2hi(Cv[p]) * scC;
            float d0 = f2lo(Dv[p]) * scD, d1 = f2hi(Dv[p]) * scD;
            size_t q0 = (size_t)(2 * p) * N, q1 = (size_t)(2 * p + 1) * N;
            if (storer) {
                if (vA) { g_logits[q0 + rA] = a0; g_logits[q1 + rA] = a1; }
                if (vB) { g_logits[q0 + rB] = b0; g_logits[q1 + rB] = b1; }
                if (vC) { g_logits[q0 + rC] = c0; g_logits[q1 + rC] = c1; }
                if (vD) { g_logits[q0 + rD] = d0; g_logits[q1 + rD] = d1; }
            }
            float m0 = fmaxf(fmaxf(vA ? a0 : -1e30f, vB ? b0 : -1e30f),
                             fmaxf(vC ? c0 : -1e30f, vD ? d0 : -1e30f));
            float m1 = fmaxf(fmaxf(vA ? a1 : -1e30f, vB ? b1 : -1e30f),
                             fmaxf(vC ? c1 : -1e30f, vD ? d1 : -1e30f));
            m0 = fmaxf(m0, __shfl_xor_sync(0xffffffffu, m0, 16));
            m1 = fmaxf(m1, __shfl_xor_sync(0xffffffffu, m1, 16));
            if (lane == 0) {
                s_wmax[warp][2 * p] = fmaxf(s_wmax[warp][2 * p], m0);
                s_wmax[warp][2 * p + 1] = fmaxf(s_wmax[warp][2 * p + 1], m1);
            }
        }

        // rotate row offsets (matches refill addressing)
#pragma unroll
        for (int j = 0; j < K1_RPW; j++) {
            int rn = row0n + j;
            if (rn > N - 1) rn = N - 1;
            ro[j] = rn * C_DIM + 4 * lane;
        }
    }

    __syncthreads();
    if (t < NQ) {
        float m = -1e30f;
#pragma unroll
        for (int w = 0; w < K1_WARPS; w++) m = fmaxf(m, s_wmax[w][t]);
        g_bmax[(size_t)blockIdx.x * NQ + t] = m;
    }
}

// ============================================================
// K1.5b: Z[q] = sum_n exp(l - M); M merged from g_bmax in-kernel
// (grid = NQ*64 blocks; part 0 publishes g_M[q])
// ============================================================
__global__ void k15b_z(int N, int nbmax) {
    int q = blockIdx.x >> 6, part = blockIdx.x & 63;
    int t = threadIdx.x;
    __shared__ float red[256];

    float m = -1e30f;
    for (int b = t; b < nbmax; b += 256)
        m = fmaxf(m, g_bmax[(size_t)b * NQ + q]);
    red[t] = m;
    __syncthreads();
    for (int s = 128; s > 0; s >>= 1) {
        if (t < s) red[t] = fmaxf(red[t], red[t + s]);
        __syncthreads();
    }
    float M = red[0];
    if (part == 0 && t == 0) g_M[q] = M;
    __syncthreads();

    const float* l = g_logits + (size_t)q * N;
    float s = 0.f;
    int n4 = N >> 2;
    int stride = 64 * 256;
    for (int i = part * 256 + t; i < n4; i += stride) {
        float4 v = *(const float4*)(l + 4 * i);
        s += __expf(v.x - M) + __expf(v.y - M) + __expf(v.z - M) + __expf(v.w - M);
    }
    for (int n = 4 * n4 + part * 256 + t; n < N; n += stride)
        s += __expf(l[n] - M);
    red[t] = s;
    __syncthreads();
    for (int st = 128; st > 0; st >>= 1) {
        if (t < st) red[t] += red[t + st];
        __syncthreads();
    }
    if (t == 0) atomicAdd(&g_Z[q], red[0]);
}

// ============================================================
// K2: balanced contiguous row range per block; chunked s_g gather
// ============================================================
__global__ __launch_bounds__(256) void k2_wsum(const float* __restrict__ X, int N) {
    __shared__ float s_g[K2_TILE];
    __shared__ float s_m[NQ], s_iz[NQ];
    int t = threadIdx.x;
    if (t < NQ) { s_m[t] = g_M[t]; s_iz[t] = (1.0f / NQ) / g_Z[t]; }
    __syncthreads();

    int r0 = (int)((long long)blockIdx.x * N / gridDim.x);
    int r1 = (int)((long long)(blockIdx.x + 1) * N / gridDim.x);

    float4 a = make_float4(0.f, 0.f, 0.f, 0.f);

    for (int n0 = r0; n0 < r1; n0 += K2_TILE) {
        int nv = min(K2_TILE, r1 - n0);
        __syncthreads();
        if (t < nv) {
            int n = n0 + t;
            float gs = 0.f;
#pragma unroll
            for (int q = 0; q < NQ; q++)
                gs = fmaf(__expf(g_logits[(size_t)q * N + n] - s_m[q]), s_iz[q], gs);
            s_g[t] = gs;
        }
        __syncthreads();

        const float* xb = X + (size_t)n0 * C_DIM + 4 * t;
        int r = 0;
        for (; r + 8 <= nv; r += 8) {
            float4 x[8];
#pragma unroll
            for (int i = 0; i < 8; i++)
                x[i] = __ldcs((const float4*)(xb + (size_t)(r + i) * C_DIM));
#pragma unroll
            for (int i = 0; i < 8; i++) {
                float g = s_g[r + i];
                a.x = fmaf(g, x[i].x, a.x); a.y = fmaf(g, x[i].y, a.y);
                a.z = fmaf(g, x[i].z, a.z); a.w = fmaf(g, x[i].w, a.w);
            }
        }
        for (; r < nv; r++) {
            float4 x = __ldcs((const float4*)(xb + (size_t)r * C_DIM));
            float g = s_g[r];
            a.x = fmaf(g, x.x, a.x); a.y = fmaf(g, x.y, a.y);
            a.z = fmaf(g, x.z, a.z); a.w = fmaf(g, x.w, a.w);
        }
    }
    *(float4*)(g_partial + (size_t)blockIdx.x * C_DIM + 4 * t) = a;
}

// ============================================================
// K2.5: pooled[c] = sum_b partial[b][c]   (grid 64 x 128)
// ============================================================
__global__ void k25_reduce(int nblocks) {
    int cpart = blockIdx.x & 7;
    int bpart = blockIdx.x >> 3;
    int c = cpart * 128 + threadIdx.x;
    float s = 0.f;
    for (int bb = bpart; bb < nblocks; bb += 8)
        s += g_partial[(size_t)bb * C_DIM + c];
    atomicAdd(&g_pooled[c], s);
}

// ============================================================
// K3: out[j] = b[j] + sum_c pooled[c]*W[j][c]   (grid 128 x 256)
// ============================================================
__global__ __launch_bounds__(256) void k3_linear(const float* __restrict__ W,
                                                 const float* __restrict__ bias,
                                                 float* __restrict__ out) {
    int t = threadIdx.x;
    int j0 = blockIdx.x * 8;
    float4 p = *(const float4*)(g_pooled + 4 * t);
    float part[8];
#pragma unroll
    for (int j = 0; j < 8; j++) {
        const float4 w = *(const float4*)(W + (size_t)(j0 + j) * C_DIM + 4 * t);
        part[j] = fmaf(p.x, w.x, fmaf(p.y, w.y, fmaf(p.z, w.z, p.w * w.w)));
    }
#pragma unroll
    for (int j = 0; j < 8; j++)
#pragma unroll
        for (int off = 16; off; off >>= 1)
            part[j] += __shfl_xor_sync(0xffffffffu, part[j], off);
    __shared__ float s_p[8][8];
    int warp = t >> 5, lane = t & 31;
    if (lane == 0)
#pragma unroll
        for (int j = 0; j < 8; j++) s_p[warp][j] = part[j];
    __syncthreads();
    if (t < 8) {
        float s = 0.f;
#pragma unroll
        for (int w = 0; w < 8; w++) s += s_p[w][t];
        out[j0 + t] = s + bias[j0 + t];
    }
}

// ============================================================
extern "C" void kernel_launch(void* const* d_in, const int* in_sizes, int n_in,
                              void* d_out, int out_size) {
    const float* X = (const float*)d_in[0];
    const float* Q = (const float*)d_in[1];
    const float* W = (const float*)d_in[2];
    const float* b = (const float*)d_in[3];
    float* out = (float*)d_out;

    int N = in_sizes[0] / C_DIM;
    if (N > MAXN) N = MAXN;

    int k1_tiles = (N + K1_RPB - 1) / K1_RPB;
    int k1_grid = (K1_GRID < k1_tiles) ? K1_GRID : k1_tiles;
    int k2_grid = (K2_GRID < N) ? K2_GRID : N;

    k0_prep<<<1, 128>>>(Q);
    k1_logits<<<k1_grid, 256>>>(X, N, k1_tiles);
    k15b_z<<<NQ * 64, 256>>>(N, k1_grid);
    k2_wsum<<<k2_grid, 256>>>(X, N);
    k25_reduce<<<64, 128>>>(k2_grid);
    k3_linear<<<128, 256>>>(W, b, out);
}